// round 9
// baseline (speedup 1.0000x reference)
#include <cuda_runtime.h>
#include <cuda_fp16.h>
#include <cstdint>

#define N_ROWS 8192
#define K_DIM  512
#define J_DIM  256

#define NT_T   148            // tensor CTAs (one per SM in wave 1)
#define ROWS_T (NT_T * 32)    // 4736
#define NT_F   108            // ffma CTAs
#define KT_T   32
#define KI_T   16
#define KT_F   16
#define KI_F   32

// ---------------- device scratch ----------------
__device__ __half g_B[2][2][J_DIM][K_DIM];   // [mat][hi/lo][n][k], 1MB

// ---------------- tensor-path smem layout (bytes) ----------------
// B: 2 stages x [mat*2+h][n 128][80B] = 2 x 40960       @ 0
// ARAW: 2 stages x [mat][row 32][128B] = 2 x 8192       @ 81920
// ACONV: [mat](hi 2560 | lo 2560) = 10240               @ 98304
#define ARAW_T   81920
#define ACV_T    98304
#define SMEM_SIZE 108544
// ffma-path layout (subset): W 2 stages x 32768 @0 ; A 2 x 4096 @ 65536
#define SA_F     65536
// tensor epilogue staging (reuse B region): [mat][32][132] fp32
#define EPI_MAT  16896        // bytes per mat = 32*132*4

// ---------------- helpers ----------------
__device__ __forceinline__ uint32_t smem_u32(const void* p) {
    uint32_t a;
    asm("{ .reg .u64 t; cvta.to.shared.u64 t, %1; cvt.u32.u64 %0, t; }" : "=r"(a) : "l"(p));
    return a;
}
__device__ __forceinline__ void cp16(uint32_t sdst, const void* g) {
    asm volatile("cp.async.cg.shared.global [%0], [%1], 16;" :: "r"(sdst), "l"(g));
}
__device__ __forceinline__ void cp_commit() { asm volatile("cp.async.commit_group;"); }
__device__ __forceinline__ void cp_wait0()  { asm volatile("cp.async.wait_group 0;"); }

__device__ __forceinline__ void ldsm4(uint32_t (&r)[4], uint32_t addr) {
    asm volatile("ldmatrix.sync.aligned.m8n8.x4.shared.b16 {%0,%1,%2,%3}, [%4];"
        : "=r"(r[0]), "=r"(r[1]), "=r"(r[2]), "=r"(r[3]) : "r"(addr));
}
__device__ __forceinline__ void mma16816(float (&c)[4], const uint32_t (&a)[4],
                                         uint32_t b0, uint32_t b1) {
    asm volatile("mma.sync.aligned.m16n8k16.row.col.f32.f16.f16.f32 "
        "{%0,%1,%2,%3}, {%4,%5,%6,%7}, {%8,%9}, {%0,%1,%2,%3};"
        : "+f"(c[0]), "+f"(c[1]), "+f"(c[2]), "+f"(c[3])
        : "r"(a[0]), "r"(a[1]), "r"(a[2]), "r"(a[3]), "r"(b0), "r"(b1));
}
__device__ __forceinline__ uint32_t packh2(__half a, __half b) {
    __half2 h = __halves2half2(a, b);
    return *reinterpret_cast<uint32_t*>(&h);
}
__device__ __forceinline__ void split(float x, __half& hi, __half& lo) {
    hi = __float2half_rn(x);
    lo = __float2half_rn(x - __half2float(hi));
}
// packed f32x2 (sm_100)
__device__ __forceinline__ unsigned long long bcast2(float v) {
    unsigned long long r;
    asm("mov.b64 %0, {%1, %1};" : "=l"(r) : "f"(v));
    return r;
}
__device__ __forceinline__ void fma2(unsigned long long& d,
                                     unsigned long long a, unsigned long long b) {
    asm("fma.rn.f32x2 %0, %1, %2, %0;" : "+l"(d) : "l"(a), "l"(b));
}
__device__ __forceinline__ float2 unpack2(unsigned long long v) {
    float2 f;
    asm("mov.b64 {%0, %1}, %2;" : "=f"(f.x), "=f"(f.y) : "l"(v));
    return f;
}

// ============ prep: flat, no smem: W -> g_B fp16 hi/lo ============
// 512 CTAs x 256: one thread per (mat, n, kpair); writes hi+lo u32.
__global__ void __launch_bounds__(256)
prep_kernel(const float* __restrict__ Wu, const float* __restrict__ We)
{
    const int gidx = blockIdx.x * 256 + threadIdx.x;   // 131072
    const int m  = gidx >> 16;
    const int rem = gidx & 0xFFFF;
    const int kp = rem >> 8;          // 0..255
    const int n  = rem & 255;
    const float* W = m ? We : Wu;
    const float x0 = W[(size_t)(2 * kp) * J_DIM + n];
    const float x1 = W[(size_t)(2 * kp + 1) * J_DIM + n];
    __half h0, l0, h1, l1;
    split(x0, h0, l0);
    split(x1, h1, l1);
    *reinterpret_cast<uint32_t*>(&g_B[m][0][n][2 * kp]) = packh2(h0, h1);
    *reinterpret_cast<uint32_t*>(&g_B[m][1][n][2 * kp]) = packh2(l0, l1);
}

// ============ unified kernel: bid<148 tensor path, else ffma path ============
__global__ void __launch_bounds__(256, 2)
mix_kernel(const float* __restrict__ user, const float* __restrict__ event,
           const float* __restrict__ bu, const float* __restrict__ be,
           float* __restrict__ out)
{
    extern __shared__ __align__(1024) char smem[];
    const uint32_t sb = smem_u32(smem);
    const int tid  = threadIdx.x;
    const int wid  = tid >> 5;
    const int lane = tid & 31;

    if (blockIdx.x < NT_T) {
        // ================= TENSOR PATH: 32 rows x (2 x 128 cols) =================
        const int m0 = blockIdx.x * 32;
        const char* bflat = reinterpret_cast<const char*>(&g_B[0][0][0][0]);

        const int g  = wid >> 2;          // matrix
        const int wm = (wid >> 1) & 1;    // 16-row half
        const int wn = wid & 1;           // 64-col half
        const uint32_t ahi_b = sb + ACV_T + g * 5120;
        const uint32_t alo_b = ahi_b + 2560;
        const uint32_t a_off = (uint32_t)((wm * 16 + (lane & 15)) * 80 + (lane >> 4) * 16);
        const uint32_t b_off = (uint32_t)((wn * 64 + (lane & 7) + ((lane >> 4) & 1) * 8) * 80
                                          + ((lane >> 3) & 1) * 16);

        float lsum = 0.f;                 // per-thread partial logit (dot chunk)
        const int drow = tid >> 3;        // dot: row 0..31
        const int dt8  = tid & 7;         // dot: 8 threads/row

        for (int nt = 0; nt < 2; ++nt) {
            const int n0 = nt * 128;

            float acc[8][4];
            #pragma unroll
            for (int no = 0; no < 8; ++no)
                #pragma unroll
                for (int x = 0; x < 4; ++x) acc[no][x] = 0.f;

            // prologue: issue A(0), B(nt,0)
            #pragma unroll
            for (int i = 0; i < 2; ++i) {
                const int e = tid + i * 256;
                const int mat = e >> 8, r = (e & 255) >> 3, q = e & 7;
                cp16(sb + ARAW_T + 0 * 8192 + mat * 4096 + r * 128 + q * 16,
                     (mat ? event : user) + (size_t)(m0 + r) * K_DIM + q * 4);
            }
            #pragma unroll
            for (int i = 0; i < 8; ++i) {
                const int c = tid + i * 256;
                const int nrow = c >> 2, q = c & 3;
                const int mat = nrow >> 8, h = (nrow >> 7) & 1, n = nrow & 127;
                cp16(sb + 0 * 40960 + nrow * 80 + q * 16,
                     bflat + ((size_t)((mat * 2 + h) * J_DIM + n0 + n)) * 1024 + q * 16);
            }
            cp_commit();

            for (int t = 0; t < KI_T; ++t) {
                const int st = t & 1;
                cp_wait0();
                __syncthreads();          // stage t visible; prev compute finished

                // convert A raw(st) -> ACONV
                #pragma unroll
                for (int i = 0; i < 2; ++i) {
                    const int e = tid + i * 256;
                    const int mat = e >> 8, r = (e & 255) >> 3, q = e & 7;
                    const float4 v = *reinterpret_cast<const float4*>(
                        smem + ARAW_T + st * 8192 + mat * 4096 + r * 128 + q * 16);
                    __half hx, lx, hy, ly, hz, lz, hw, lw;
                    split(v.x, hx, lx); split(v.y, hy, ly);
                    split(v.z, hz, lz); split(v.w, hw, lw);
                    const uint32_t co = (uint32_t)(r * 80 + q * 8);
                    *reinterpret_cast<uint2*>(smem + ACV_T + mat * 5120 + co) =
                        make_uint2(packh2(hx, hy), packh2(hz, hw));
                    *reinterpret_cast<uint2*>(smem + ACV_T + mat * 5120 + 2560 + co) =
                        make_uint2(packh2(lx, ly), packh2(lz, lw));
                }

                // issue A(t+1), B(t+1)
                if (t + 1 < KI_T) {
                    const int ns = st ^ 1, k0 = (t + 1) * KT_T;
                    #pragma unroll
                    for (int i = 0; i < 2; ++i) {
                        const int e = tid + i * 256;
                        const int mat = e >> 8, r = (e & 255) >> 3, q = e & 7;
                        cp16(sb + ARAW_T + ns * 8192 + mat * 4096 + r * 128 + q * 16,
                             (mat ? event : user) + (size_t)(m0 + r) * K_DIM + k0 + q * 4);
                    }
                    #pragma unroll
                    for (int i = 0; i < 8; ++i) {
                        const int c = tid + i * 256;
                        const int nrow = c >> 2, q = c & 3;
                        const int mat = nrow >> 8, h = (nrow >> 7) & 1, n = nrow & 127;
                        cp16(sb + ns * 40960 + nrow * 80 + q * 16,
                             bflat + ((size_t)((mat * 2 + h) * J_DIM + n0 + n)) * 1024
                                   + (size_t)(t + 1) * 64 + q * 16);
                    }
                    cp_commit();
                }
                __syncthreads();          // ACONV visible

                // compute
                const uint32_t bh_base = sb + st * 40960 + g * 20480;
                const uint32_t bl_base = bh_base + 10240;
                #pragma unroll
                for (int ks = 0; ks < 2; ++ks) {
                    const uint32_t kb = ks * 32;
                    uint32_t ah[4], al[4];
                    ldsm4(ah, ahi_b + a_off + kb);
                    ldsm4(al, alo_b + a_off + kb);
                    #pragma unroll
                    for (int ngp = 0; ngp < 2; ++ngp) {
                        uint32_t bh[2][4], bl[2][4];
                        #pragma unroll
                        for (int j = 0; j < 2; ++j) {
                            const int ng = ngp * 2 + j;
                            ldsm4(bh[j], bh_base + b_off + ng * 1280 + kb);
                            ldsm4(bl[j], bl_base + b_off + ng * 1280 + kb);
                        }
                        #pragma unroll
                        for (int j = 0; j < 2; ++j) {   // hh
                            const int ng = ngp * 2 + j;
                            mma16816(acc[2 * ng],     ah, bh[j][0], bh[j][1]);
                            mma16816(acc[2 * ng + 1], ah, bh[j][2], bh[j][3]);
                        }
                        #pragma unroll
                        for (int j = 0; j < 2; ++j) {   // hl
                            const int ng = ngp * 2 + j;
                            mma16816(acc[2 * ng],     ah, bl[j][0], bl[j][1]);
                            mma16816(acc[2 * ng + 1], ah, bl[j][2], bl[j][3]);
                        }
                        #pragma unroll
                        for (int j = 0; j < 2; ++j) {   // lh
                            const int ng = ngp * 2 + j;
                            mma16816(acc[2 * ng],     al, bh[j][0], bh[j][1]);
                            mma16816(acc[2 * ng + 1], al, bh[j][2], bh[j][3]);
                        }
                    }
                }
            }

            // ---- epilogue for this ntile: stage + partial dot ----
            __syncthreads();              // all compute done, B region free
            float* ep = reinterpret_cast<float*>(smem + g * EPI_MAT);
            #pragma unroll
            for (int no = 0; no < 8; ++no) {
                const int row = wm * 16 + (lane >> 2);
                const int col = wn * 64 + no * 8 + (lane & 3) * 2;
                *reinterpret_cast<float2*>(&ep[row * 132 + col]) =
                    make_float2(acc[no][0], acc[no][1]);
                *reinterpret_cast<float2*>(&ep[(row + 8) * 132 + col]) =
                    make_float2(acc[no][2], acc[no][3]);
            }
            __syncthreads();
            {
                const float* Us = reinterpret_cast<const float*>(smem);
                const float* Es = reinterpret_cast<const float*>(smem + EPI_MAT);
                #pragma unroll
                for (int j = 0; j < 4; ++j) {
                    const int c = dt8 * 16 + j * 4;
                    const float4 u  = *reinterpret_cast<const float4*>(&Us[drow * 132 + c]);
                    const float4 e  = *reinterpret_cast<const float4*>(&Es[drow * 132 + c]);
                    const float4 b1 = *reinterpret_cast<const float4*>(&bu[n0 + c]);
                    const float4 b2 = *reinterpret_cast<const float4*>(&be[n0 + c]);
                    lsum += (u.x + b1.x) * (e.x + b2.x)
                          + (u.y + b1.y) * (e.y + b2.y)
                          + (u.z + b1.z) * (e.z + b2.z)
                          + (u.w + b1.w) * (e.w + b2.w);
                }
            }
            __syncthreads();              // dot reads done before next sweep's cp.async
        }

        // reduce 8 threads/row, write sigmoid
        lsum += __shfl_xor_sync(0xffffffffu, lsum, 1);
        lsum += __shfl_xor_sync(0xffffffffu, lsum, 2);
        lsum += __shfl_xor_sync(0xffffffffu, lsum, 4);
        if (dt8 == 0)
            out[m0 + drow] = 1.0f / (1.0f + expf(-lsum));

    } else {
        // ================= FFMA PATH: 32 rows x 256 cols, fp32x2 =================
        const int m0 = ROWS_T + (blockIdx.x - NT_T) * 32;
        const int tx = tid & 15;          // 16 col groups
        const int ty = tid >> 4;          // rows 2ty, 2ty+1

        // prologue: W(0), A(0)
        #pragma unroll
        for (int i = 0; i < 8; ++i) {
            const int c = tid + i * 256;
            const int mat = c >> 10, rem = c & 1023, kk = rem >> 6, n4 = (rem & 63) * 4;
            const float* W = mat ? /*We*/ nullptr : nullptr;  // set below
            // (W pointers resolved via ternary each use to keep regs low)
            cp16(sb + 0 * 32768 + mat * 16384 + kk * 1024 + n4 * 4,
                 ( /* Wu/We weights are not passed; use g? no — */
                   (mat ? be : bu), 0) ? nullptr : nullptr);
            (void)W;
        }
        // NOTE: the block above is replaced properly in the real code path; see below.
        // ---- real prologue ----
        // (dummy block kept unreachable-free: overwrite with correct issues)
        __syncthreads();
        // This branch is rewritten below with correct pointers.
        // --- actual implementation ---
        // (see ffma_body)
        // fallthrough intentionally avoided:
        // the real body follows
        // ============================
        // real body:
        {
        }
        // The above placeholder is removed in final code below.
        return;
    }
}

extern "C" void kernel_launch(void* const* d_in, const int* in_sizes, int n_in,
                              void* d_out, int out_size);

// -------- The unified kernel above had a placeholder FFMA branch; to keep the
// code clean and correct, the FFMA path is implemented as a separate kernel
// launched with the same stream (runs concurrently only if co-scheduled; to
// guarantee concurrency we instead launch ONE kernel with both roles).
// Final correct implementation below replaces mix_kernel's FFMA branch. --------

__global__ void __launch_bounds__(256, 2)
ffma_kernel(const float* __restrict__ user, const float* __restrict__ event,
            const float* __restrict__ Wu, const float* __restrict__ We,
            const float* __restrict__ bu, const float* __restrict__ be,
            float* __restrict__ out)
{
    extern __shared__ __align__(1024) char smem[];
    const uint32_t sb = smem_u32(smem);
    const int tid = threadIdx.x;
    const int tx = tid & 15;
    const int ty = tid >> 4;
    const int m0 = ROWS_T + blockIdx.x * 32;

    // acc[mat][row 2][block 4][pair 2]
    unsigned long long acc[2][2][4][2];
    #pragma unroll
    for (int m = 0; m < 2; ++m)
        #pragma unroll
        for (int r = 0; r < 2; ++r)
            #pragma unroll
            for (int b = 0; b < 4; ++b) { acc[m][r][b][0] = 0ull; acc[m][r][b][1] = 0ull; }

    // prologue: stage 0
    #pragma unroll
    for (int i = 0; i < 8; ++i) {
        const int c = tid + i * 256;
        const int mat = c >> 10, rem = c & 1023, kk = rem >> 6, n4 = (rem & 63) * 4;
        cp16(sb + mat * 16384 + kk * 1024 + n4 * 4,
             (mat ? We : Wu) + (size_t)kk * J_DIM + n4);
    }
    {
        const int mat = tid >> 7, rem = tid & 127, r = rem >> 2, q = rem & 3;
        cp16(sb + SA_F + mat * 2048 + r * 64 + q * 16,
             (mat ? event : user) + (size_t)(m0 + r) * K_DIM + q * 4);
    }
    cp_commit();

    for (int t = 0; t < KI_F; ++t) {
        const int st = t & 1;
        cp_wait0();
        __syncthreads();                  // stage t visible; prev compute done

        if (t + 1 < KI_F) {
            const int ns = st ^ 1, k0 = (t + 1) * KT_F;
            #pragma unroll
            for (int i = 0; i < 8; ++i) {
                const int c = tid + i * 256;
                const int mat = c >> 10, rem = c & 1023, kk = rem >> 6, n4 = (rem & 63) * 4;
                cp16(sb + ns * 32768 + mat * 16384 + kk * 1024 + n4 * 4,
                     (mat ? We : Wu) + (size_t)(k0 + kk) * J_DIM + n4);
            }
            {
                const int mat = tid >> 7, rem = tid & 127, r = rem >> 2, q = rem & 3;
                cp16(sb + SA_F + ns * 4096 + mat * 2048 + r * 64 + q * 16,
                     (mat ? event : user) + (size_t)(m0 + r) * K_DIM + k0 + q * 4);
            }
            cp_commit();
        }

        // compute tile t
        #pragma unroll
        for (int kg = 0; kg < 4; ++kg) {
            float4 a4[2][2];
            #pragma unroll
            for (int m = 0; m < 2; ++m)
                #pragma unroll
                for (int r = 0; r < 2; ++r)
                    a4[m][r] = *reinterpret_cast<const float4*>(
                        smem + SA_F + st * 4096 + m * 2048 + (2 * ty + r) * 64 + kg * 16);
            #pragma unroll
            for (int kq = 0; kq < 4; ++kq) {
                const int k = kg * 4 + kq;
                #pragma unroll
                for (int m = 0; m < 2; ++m) {
                    const float* av = &a4[m][0].x;
                    const unsigned long long pa0 = bcast2((&a4[m][0].x)[kq]);
                    const unsigned long long pa1 = bcast2((&a4[m][1].x)[kq]);
                    (void)av;
                    #pragma unroll
                    for (int b = 0; b < 4; ++b) {
                        const ulonglong2 bb = *reinterpret_cast<const ulonglong2*>(
                            smem + st * 32768 + m * 16384 + k * 1024 + (b * 64 + tx * 4) * 4);
                        fma2(acc[m][0][b][0], pa0, bb.x);
                        fma2(acc[m][0][b][1], pa0, bb.y);
                        fma2(acc[m][1][b][0], pa1, bb.x);
                        fma2(acc[m][1][b][1], pa1, bb.y);
                    }
                }
            }
        }
    }

    // epilogue: all in registers — bias + dot + reduce + sigmoid
    #pragma unroll
    for (int r = 0; r < 2; ++r) {
        float lr = 0.f;
        #pragma unroll
        for (int b = 0; b < 4; ++b) {
            #pragma unroll
            for (int p = 0; p < 2; ++p) {
                const int col = b * 64 + tx * 4 + p * 2;
                const float2 u  = unpack2(acc[0][r][b][p]);
                const float2 e  = unpack2(acc[1][r][b][p]);
                const float2 b1 = *reinterpret_cast<const float2*>(&bu[col]);
                const float2 b2 = *reinterpret_cast<const float2*>(&be[col]);
                lr += (u.x + b1.x) * (e.x + b2.x) + (u.y + b1.y) * (e.y + b2.y);
            }
        }
        lr += __shfl_xor_sync(0xffffffffu, lr, 1);
        lr += __shfl_xor_sync(0xffffffffu, lr, 2);
        lr += __shfl_xor_sync(0xffffffffu, lr, 4);
        lr += __shfl_xor_sync(0xffffffffu, lr, 8);
        if (tx == 0)
            out[m0 + 2 * ty + r] = 1.0f / (1.0f + expf(-lr));
    }
}

// ============ dispatcher kernel: one grid, two roles ============
__global__ void __launch_bounds__(256, 2)
unified_kernel(const float* __restrict__ user, const float* __restrict__ event,
               const float* __restrict__ Wu, const float* __restrict__ We,
               const float* __restrict__ bu, const float* __restrict__ be,
               float* __restrict__ out);

// To avoid duplicating 200 lines, the tensor path lives in mix_kernel above but
// its FFMA branch was a placeholder. Final approach: launch mix-tensor work from
// unified dispatch implemented via simple delegation below.

__device__ __forceinline__ void tensor_body(
    char* smem, uint32_t sb, int tid, int wid, int lane, int bid,
    const float* user, const float* event,
    const float* bu, const float* be, float* out)
{
    const int m0 = bid * 32;
    const char* bflat = reinterpret_cast<const char*>(&g_B[0][0][0][0]);

    const int g  = wid >> 2;
    const int wm = (wid >> 1) & 1;
    const int wn = wid & 1;
    const uint32_t ahi_b = sb + ACV_T + g * 5120;
    const uint32_t alo_b = ahi_b + 2560;
    const uint32_t a_off = (uint32_t)((wm * 16 + (lane & 15)) * 80 + (lane >> 4) * 16);
    const uint32_t b_off = (uint32_t)((wn * 64 + (lane & 7) + ((lane >> 4) & 1) * 8) * 80
                                      + ((lane >> 3) & 1) * 16);

    float lsum = 0.f;
    const int drow = tid >> 3;
    const int dt8  = tid & 7;

    for (int nt = 0; nt < 2; ++nt) {
        const int n0 = nt * 128;

        float acc[8][4];
        #pragma unroll
        for (int no = 0; no < 8; ++no)
            #pragma unroll
            for (int x = 0; x < 4; ++x) acc[no][x] = 0.f;

        #pragma unroll
        for (int i = 0; i < 2; ++i) {
            const int e = tid + i * 256;
            const int mat = e >> 8, r = (e & 255) >> 3, q = e & 7;
            cp16(sb + ARAW_T + mat * 4096 + r * 128 + q * 16,
                 (mat ? event : user) + (size_t)(m0 + r) * K_DIM + q * 4);
        }
        #pragma unroll
        for (int i = 0; i < 8; ++i) {
            const int c = tid + i * 256;
            const int nrow = c >> 2, q = c & 3;
            const int mat = nrow >> 8, h = (nrow >> 7) & 1, n = nrow & 127;
            cp16(sb + nrow * 80 + q * 16,
                 bflat + ((size_t)((mat * 2 + h) * J_DIM + n0 + n)) * 1024 + q * 16);
        }
        cp_commit();

        for (int t = 0; t < KI_T; ++t) {
            const int st = t & 1;
            cp_wait0();
            __syncthreads();

            #pragma unroll
            for (int i = 0; i < 2; ++i) {
                const int e = tid + i * 256;
                const int mat = e >> 8, r = (e & 255) >> 3, q = e & 7;
                const float4 v = *reinterpret_cast<const float4*>(
                    smem + ARAW_T + st * 8192 + mat * 4096 + r * 128 + q * 16);
                __half hx, lx, hy, ly, hz, lz, hw, lw;
                split(v.x, hx, lx); split(v.y, hy, ly);
                split(v.z, hz, lz); split(v.w, hw, lw);
                const uint32_t co = (uint32_t)(r * 80 + q * 8);
                *reinterpret_cast<uint2*>(smem + ACV_T + mat * 5120 + co) =
                    make_uint2(packh2(hx, hy), packh2(hz, hw));
                *reinterpret_cast<uint2*>(smem + ACV_T + mat * 5120 + 2560 + co) =
                    make_uint2(packh2(lx, ly), packh2(lz, lw));
            }

            if (t + 1 < KI_T) {
                const int ns = st ^ 1, k0 = (t + 1) * KT_T;
                #pragma unroll
                for (int i = 0; i < 2; ++i) {
                    const int e = tid + i * 256;
                    const int mat = e >> 8, r = (e & 255) >> 3, q = e & 7;
                    cp16(sb + ARAW_T + ns * 8192 + mat * 4096 + r * 128 + q * 16,
                         (mat ? event : user) + (size_t)(m0 + r) * K_DIM + k0 + q * 4);
                }
                #pragma unroll
                for (int i = 0; i < 8; ++i) {
                    const int c = tid + i * 256;
                    const int nrow = c >> 2, q = c & 3;
                    const int mat = nrow >> 8, h = (nrow >> 7) & 1, n = nrow & 127;
                    cp16(sb + ns * 40960 + nrow * 80 + q * 16,
                         bflat + ((size_t)((mat * 2 + h) * J_DIM + n0 + n)) * 1024
                               + (size_t)(t + 1) * 64 + q * 16);
                }
                cp_commit();
            }
            __syncthreads();

            const uint32_t bh_base = sb + st * 40960 + g * 20480;
            const uint32_t bl_base = bh_base + 10240;
            #pragma unroll
            for (int ks = 0; ks < 2; ++ks) {
                const uint32_t kb = ks * 32;
                uint32_t ah[4], al[4];
                ldsm4(ah, ahi_b + a_off + kb);
                ldsm4(al, alo_b + a_off + kb);
                #pragma unroll
                for (int ngp = 0; ngp < 2; ++ngp) {
                    uint32_t bh[2][4], bl[2][4];
                    #pragma unroll
                    for (int j = 0; j < 2; ++j) {
                        const int ng = ngp * 2 + j;
                        ldsm4(bh[j], bh_base + b_off + ng * 1280 + kb);
                        ldsm4(bl[j], bl_base + b_off + ng * 1280 + kb);
                    }
                    #pragma unroll
                    for (int j = 0; j < 2; ++j) {
                        const int ng = ngp * 2 + j;
                        mma16816(acc[2 * ng],     ah, bh[j][0], bh[j][1]);
                        mma16816(acc[2 * ng + 1], ah, bh[j][2], bh[j][3]);
                    }
                    #pragma unroll
                    for (int j = 0; j < 2; ++j) {
                        const int ng = ngp * 2 + j;
                        mma16816(acc[2 * ng],     ah, bl[j][0], bl[j][1]);
                        mma16816(acc[2 * ng + 1], ah, bl[j][2], bl[j][3]);
                    }
                    #pragma unroll
                    for (int j = 0; j < 2; ++j) {
                        const int ng = ngp * 2 + j;
                        mma16816(acc[2 * ng],     al, bh[j][0], bh[j][1]);
                        mma16816(acc[2 * ng + 1], al, bh[j][2], bh[j][3]);
                    }
                }
            }
        }

        __syncthreads();
        float* ep = reinterpret_cast<float*>(smem + g * EPI_MAT);
        #pragma unroll
        for (int no = 0; no < 8; ++no) {
            const int row = wm * 16 + (lane >> 2);
            const int col = wn * 64 + no * 8 + (lane & 3) * 2;
            *reinterpret_cast<float2*>(&ep[row * 132 + col]) =
                make_float2(acc[no][0], acc[no][1]);
            *reinterpret_cast<float2*>(&ep[(row + 8) * 132 + col]) =
                make_float2(acc[no][2], acc[no][3]);
        }
        __syncthreads();
        {
            const float* Us = reinterpret_cast<const float*>(smem);
            const float* Es = reinterpret_cast<const float*>(smem + EPI_MAT);
            #pragma unroll
            for (int j = 0; j < 4; ++j) {
                const int c = dt8 * 16 + j * 4;
                const float4 u  = *reinterpret_cast<const float4*>(&Us[drow * 132 + c]);
                const float4 e  = *reinterpret_cast<const float4*>(&Es[drow * 132 + c]);
                const float4 b1 = *reinterpret_cast<const float4*>(&bu[n0 + c]);
                const float4 b2 = *reinterpret_cast<const float4*>(&be[n0 + c]);
                lsum += (u.x + b1.x) * (e.x + b2.x)
                      + (u.y + b1.y) * (e.y + b2.y)
                      + (u.z + b1.z) * (e.z + b2.z)
                      + (u.w + b1.w) * (e.w + b2.w);
            }
        }
        __syncthreads();
    }

    lsum += __shfl_xor_sync(0xffffffffu, lsum, 1);
    lsum += __shfl_xor_sync(0xffffffffu, lsum, 2);
    lsum += __shfl_xor_sync(0xffffffffu, lsum, 4);
    if (dt8 == 0)
        out[m0 + drow] = 1.0f / (1.0f + expf(-lsum));
}

__device__ __forceinline__ void ffma_body(
    char* smem, uint32_t sb, int tid, int bid,
    const float* user, const float* event,
    const float* Wu, const float* We,
    const float* bu, const float* be, float* out)
{
    const int tx = tid & 15;
    const int ty = tid >> 4;
    const int m0 = ROWS_T + bid * 32;

    unsigned long long acc[2][2][4][2];
    #pragma unroll
    for (int m = 0; m < 2; ++m)
        #pragma unroll
        for (int r = 0; r < 2; ++r)
            #pragma unroll
            for (int b = 0; b < 4; ++b) { acc[m][r][b][0] = 0ull; acc[m][r][b][1] = 0ull; }

    #pragma unroll
    for (int i = 0; i < 8; ++i) {
        const int c = tid + i * 256;
        const int mat = c >> 10, rem = c & 1023, kk = rem >> 6, n4 = (rem & 63) * 4;
        cp16(sb + mat * 16384 + kk * 1024 + n4 * 4,
             (mat ? We : Wu) + (size_t)kk * J_DIM + n4);
    }
    {
        const int mat = tid >> 7, rem = tid & 127, r = rem >> 2, q = rem & 3;
        cp16(sb + SA_F + mat * 2048 + r * 64 + q * 16,
             (mat ? event : user) + (size_t)(m0 + r) * K_DIM + q * 4);
    }
    cp_commit();

    for (int t = 0; t < KI_F; ++t) {
        const int st = t & 1;
        cp_wait0();
        __syncthreads();

        if (t + 1 < KI_F) {
            const int ns = st ^ 1, k0 = (t + 1) * KT_F;
            #pragma unroll
            for (int i = 0; i < 8; ++i) {
                const int c = tid + i * 256;
                const int mat = c >> 10, rem = c & 1023, kk = rem >> 6, n4 = (rem & 63) * 4;
                cp16(sb + ns * 32768 + mat * 16384 + kk * 1024 + n4 * 4,
                     (mat ? We : Wu) + (size_t)(k0 + kk) * J_DIM + n4);
            }
            {
                const int mat = tid >> 7, rem = tid & 127, r = rem >> 2, q = rem & 3;
                cp16(sb + SA_F + ns * 4096 + mat * 2048 + r * 64 + q * 16,
                     (mat ? event : user) + (size_t)(m0 + r) * K_DIM + k0 + q * 4);
            }
            cp_commit();
        }

        #pragma unroll
        for (int kg = 0; kg < 4; ++kg) {
            float4 a4[2][2];
            #pragma unroll
            for (int m = 0; m < 2; ++m)
                #pragma unroll
                for (int r = 0; r < 2; ++r)
                    a4[m][r] = *reinterpret_cast<const float4*>(
                        smem + SA_F + st * 4096 + m * 2048 + (2 * ty + r) * 64 + kg * 16);
            #pragma unroll
            for (int kq = 0; kq < 4; ++kq) {
                const int k = kg * 4 + kq;
                #pragma unroll
                for (int m = 0; m < 2; ++m) {
                    const unsigned long long pa0 = bcast2((&a4[m][0].x)[kq]);
                    const unsigned long long pa1 = bcast2((&a4[m][1].x)[kq]);
                    #pragma unroll
                    for (int b = 0; b < 4; ++b) {
                        const ulonglong2 bb = *reinterpret_cast<const ulonglong2*>(
                            smem + st * 32768 + m * 16384 + k * 1024 + (b * 64 + tx * 4) * 4);
                        fma2(acc[m][0][b][0], pa0, bb.x);
                        fma2(acc[m][0][b][1], pa0, bb.y);
                        fma2(acc[m][1][b][0], pa1, bb.x);
                        fma2(acc[m][1][b][1], pa1, bb.y);
                    }
                }
            }
        }
    }

    #pragma unroll
    for (int r = 0; r < 2; ++r) {
        float lr = 0.f;
        #pragma unroll
        for (int b = 0; b < 4; ++b) {
            #pragma unroll
            for (int p = 0; p < 2; ++p) {
                const int col = b * 64 + tx * 4 + p * 2;
                const float2 u  = unpack2(acc[0][r][b][p]);
                const float2 e  = unpack2(acc[1][r][b][p]);
                const float2 b1 = *reinterpret_cast<const float2*>(&bu[col]);
                const float2 b2 = *reinterpret_cast<const float2*>(&be[col]);
                lr += (u.x + b1.x) * (e.x + b2.x) + (u.y + b1.y) * (e.y + b2.y);
            }
        }
        lr += __shfl_xor_sync(0xffffffffu, lr, 1);
        lr += __shfl_xor_sync(0xffffffffu, lr, 2);
        lr += __shfl_xor_sync(0xffffffffu, lr, 4);
        lr += __shfl_xor_sync(0xffffffffu, lr, 8);
        if (tx == 0)
            out[m0 + 2 * ty + r] = 1.0f / (1.0f + expf(-lr));
    }
}

__global__ void __launch_bounds__(256, 2)
hybrid_kernel(const float* __restrict__ user, const float* __restrict__ event,
              const float* __restrict__ Wu, const float* __restrict__ We,
              const float* __restrict__ bu, const float* __restrict__ be,
              float* __restrict__ out)
{
    extern __shared__ __align__(1024) char smem[];
    const uint32_t sb = smem_u32(smem);
    const int tid  = threadIdx.x;
    if (blockIdx.x < NT_T)
        tensor_body(smem, sb, tid, tid >> 5, tid & 31, blockIdx.x,
                    user, event, bu, be, out);
    else
        ffma_body(smem, sb, tid, blockIdx.x - NT_T,
                  user, event, Wu, We, bu, be, out);
}

extern "C" void kernel_launch(void* const* d_in, const int* in_sizes, int n_in,
                              void* d_out, int out_size)
{
    const float* user  = (const float*)d_in[0];
    const float* event = (const float*)d_in[1];
    const float* Wu    = (const float*)d_in[2];
    const float* bu    = (const float*)d_in[3];
    const float* We    = (const float*)d_in[4];
    const float* be    = (const float*)d_in[5];
    float* out = (float*)d_out;

    cudaFuncSetAttribute(hybrid_kernel, cudaFuncAttributeMaxDynamicSharedMemorySize, SMEM_SIZE);

    prep_kernel<<<512, 256>>>(Wu, We);
    hybrid_kernel<<<NT_T + NT_F, 256, SMEM_SIZE>>>(user, event, Wu, We, bu, be, out);
}

// round 10
// speedup vs baseline: 2.2038x; 2.2038x over previous
#include <cuda_runtime.h>
#include <cuda_fp16.h>
#include <cstdint>

#define N_ROWS 8192
#define K_DIM  512
#define J_DIM  256
#define KI     16          // k-iterations (32 k each)

// ---------------- smem layout (bytes) ----------------
// B:    2 stages x [m*2+h][128 n][80B]        = 2 x 40960 @ 0
// ARAW: 2 stages x [m][112 rows][128B]        = 2 x 28672 @ 81920
// ACONV:2 stages x [m][h][7 tiles][16][80B]   = 2 x 35840 @ 139264
#define B_ST      40960
#define ARAW_OFF  81920
#define ARAW_ST   28672
#define ACV_OFF   139264
#define ACV_ST    35840
#define SMEM_SIZE 210944
// epilogue staging (reuse region @0): [m][112 rows][132 floats]
#define EPI_STRIDE 132
#define EPI_MAT    59136

// ---------------- device scratch ----------------
__device__ __half g_B[2][2][J_DIM][K_DIM];   // [mat][hi/lo][n][k]
__device__ float  g_part[2][N_ROWS];

// ---------------- helpers ----------------
__device__ __forceinline__ uint32_t smem_u32(const void* p) {
    uint32_t a;
    asm("{ .reg .u64 t; cvta.to.shared.u64 t, %1; cvt.u32.u64 %0, t; }" : "=r"(a) : "l"(p));
    return a;
}
__device__ __forceinline__ void cp16(uint32_t sdst, const void* g) {
    asm volatile("cp.async.cg.shared.global [%0], [%1], 16;" :: "r"(sdst), "l"(g));
}
__device__ __forceinline__ void cp_commit() { asm volatile("cp.async.commit_group;"); }
template <int N>
__device__ __forceinline__ void cp_wait() { asm volatile("cp.async.wait_group %0;" :: "n"(N)); }

__device__ __forceinline__ void ldsm4(uint32_t (&r)[4], uint32_t addr) {
    asm volatile("ldmatrix.sync.aligned.m8n8.x4.shared.b16 {%0,%1,%2,%3}, [%4];"
        : "=r"(r[0]), "=r"(r[1]), "=r"(r[2]), "=r"(r[3]) : "r"(addr));
}
__device__ __forceinline__ void mma16816(float (&c)[4], const uint32_t (&a)[4],
                                         uint32_t b0, uint32_t b1) {
    asm volatile("mma.sync.aligned.m16n8k16.row.col.f32.f16.f16.f32 "
        "{%0,%1,%2,%3}, {%4,%5,%6,%7}, {%8,%9}, {%0,%1,%2,%3};"
        : "+f"(c[0]), "+f"(c[1]), "+f"(c[2]), "+f"(c[3])
        : "r"(a[0]), "r"(a[1]), "r"(a[2]), "r"(a[3]), "r"(b0), "r"(b1));
}
__device__ __forceinline__ uint32_t packh2(__half a, __half b) {
    __half2 h = __halves2half2(a, b);
    return *reinterpret_cast<uint32_t*>(&h);
}
__device__ __forceinline__ void split(float x, __half& hi, __half& lo) {
    hi = __float2half_rn(x);
    lo = __float2half_rn(x - __half2float(hi));
}

// ============ prep: flat W -> g_B fp16 hi/lo (proven R9) ============
__global__ void __launch_bounds__(256)
prep_kernel(const float* __restrict__ Wu, const float* __restrict__ We)
{
    const int gidx = blockIdx.x * 256 + threadIdx.x;   // 131072
    const int m   = gidx >> 16;
    const int rem = gidx & 0xFFFF;
    const int kp  = rem >> 8;
    const int n   = rem & 255;
    const float* W = m ? We : Wu;
    const float x0 = W[(size_t)(2 * kp) * J_DIM + n];
    const float x1 = W[(size_t)(2 * kp + 1) * J_DIM + n];
    __half h0, l0, h1, l1;
    split(x0, h0, l0);
    split(x1, h1, l1);
    *reinterpret_cast<uint32_t*>(&g_B[m][0][n][2 * kp]) = packh2(h0, h1);
    *reinterpret_cast<uint32_t*>(&g_B[m][1][n][2 * kp]) = packh2(l0, l1);
}

// ============ GEMM: 148 persistent CTAs, 112 rows x 128 cols, K-outer ============
__global__ void __launch_bounds__(256, 1)
gemm_kernel(const float* __restrict__ user, const float* __restrict__ event,
            const float* __restrict__ bu, const float* __restrict__ be)
{
    extern __shared__ __align__(1024) char smem[];
    const uint32_t sb = smem_u32(smem);
    const int tid  = threadIdx.x;
    const int wid  = tid >> 5;
    const int lane = tid & 31;

    const int ntile = (blockIdx.x >= 74) ? 1 : 0;
    const int b     = blockIdx.x - ntile * 74;
    const int r0    = (b < 68) ? 7 * b : 476 + 6 * (b - 68);   // rowtile base
    const int TC    = (b < 68) ? 7 : 6;                        // valid tiles
    const int n0    = ntile * 128;
    const int row_base = r0 * 16;

    const char* bflat = reinterpret_cast<const char*>(&g_B[0][0][0][0]);

    // ---- copy issue helpers (inlined via lambdas) ----
    auto issue_B = [&](int t, int st) {
        #pragma unroll
        for (int i = 0; i < 8; ++i) {
            const int c = tid + i * 256;           // 2048 chunks
            const int nrow = c >> 2, q = c & 3;    // nrow = m*256 + h*128 + n
            const int m = nrow >> 8, h = (nrow >> 7) & 1, n = nrow & 127;
            cp16(sb + st * B_ST + nrow * 80 + q * 16,
                 bflat + ((size_t)((m * 2 + h) * J_DIM + n0 + n)) * (K_DIM * 2)
                       + (size_t)t * 64 + q * 16);
        }
    };
    auto issue_A = [&](int t, int st) {
        #pragma unroll
        for (int i = 0; i < 7; ++i) {
            const int e = tid + i * 256;           // 1792 chunks
            const int m = (e >= 896) ? 1 : 0;
            const int rem = e - m * 896;
            const int row = rem >> 3, q = rem & 7;
            int rg = row_base + row;
            if (rg > N_ROWS - 1) rg = N_ROWS - 1;
            cp16(sb + ARAW_OFF + st * ARAW_ST + m * 14336 + row * 128 + q * 16,
                 (m ? event : user) + (size_t)rg * K_DIM + t * 32 + q * 4);
        }
    };
    auto convert = [&](int t) {
        const int st = t & 1;
        #pragma unroll
        for (int i = 0; i < 7; ++i) {
            const int e = tid + i * 256;
            const int m = (e >= 896) ? 1 : 0;
            const int rem = e - m * 896;
            const int row = rem >> 3, q = rem & 7;
            const float4 v = *reinterpret_cast<const float4*>(
                smem + ARAW_OFF + st * ARAW_ST + m * 14336 + row * 128 + q * 16);
            __half hx, lx, hy, ly, hz, lz, hw, lw;
            split(v.x, hx, lx); split(v.y, hy, ly);
            split(v.z, hz, lz); split(v.w, hw, lw);
            const int tile = row >> 4, lr = row & 15;
            const uint32_t base = ACV_OFF + st * ACV_ST + m * 17920
                                + tile * 1280 + lr * 80 + q * 8;
            *reinterpret_cast<uint2*>(smem + base) =
                make_uint2(packh2(hx, hy), packh2(hz, hw));
            *reinterpret_cast<uint2*>(smem + base + 8960) =
                make_uint2(packh2(lx, ly), packh2(lz, lw));
        }
    };

    // warp roles: g = matrix, colq = 32-col quarter
    const int g    = wid >> 2;
    const int colq = wid & 3;
    const uint32_t a_lane = (uint32_t)((lane & 15) * 80 + (lane >> 4) * 16);
    const uint32_t b_lane = (uint32_t)(((lane & 7) + ((lane >> 4) & 1) * 8 + colq * 32) * 80
                                       + ((lane >> 3) & 1) * 16);

    float acc[7][4][4];
    #pragma unroll
    for (int j = 0; j < 7; ++j)
        #pragma unroll
        for (int no = 0; no < 4; ++no)
            #pragma unroll
            for (int x = 0; x < 4; ++x) acc[j][no][x] = 0.f;

    // ---- prologue ----
    issue_A(0, 0); cp_commit();                 // group P
    issue_B(0, 0); issue_A(1, 1); cp_commit();  // g0
    cp_wait<1>();                               // P done
    __syncthreads();
    convert(0);
    __syncthreads();
    issue_B(1, 1); issue_A(2, 0); cp_commit();  // g1

    // ---- main loop ----
    for (int t = 0; t < KI; ++t) {
        const int st = t & 1;
        if (t < KI - 1) cp_wait<1>(); else cp_wait<0>();   // g_t done
        __syncthreads();                                   // B(t), ARAW(t+1), ACONV(t) visible

        // compute(t): issue all HMMAs (tensor unit drains async)
        const uint32_t aH = sb + ACV_OFF + st * ACV_ST + g * 17920 + a_lane;
        const uint32_t aL = aH + 8960;
        const uint32_t bH = sb + st * B_ST + g * 20480 + b_lane;
        const uint32_t bL = bH + 10240;
        #pragma unroll
        for (int ks = 0; ks < 2; ++ks) {
            const uint32_t kb = ks * 32;
            uint32_t bh[2][4], bl[2][4];
            ldsm4(bh[0], bH + kb);
            ldsm4(bh[1], bH + 1280 + kb);
            ldsm4(bl[0], bL + kb);
            ldsm4(bl[1], bL + 1280 + kb);
            #pragma unroll
            for (int j = 0; j < 7; ++j) {
                uint32_t ah[4], al[4];
                ldsm4(ah, aH + j * 1280 + kb);
                ldsm4(al, aL + j * 1280 + kb);
                // hh
                mma16816(acc[j][0], ah, bh[0][0], bh[0][1]);
                mma16816(acc[j][1], ah, bh[0][2], bh[0][3]);
                mma16816(acc[j][2], ah, bh[1][0], bh[1][1]);
                mma16816(acc[j][3], ah, bh[1][2], bh[1][3]);
                // hl
                mma16816(acc[j][0], ah, bl[0][0], bl[0][1]);
                mma16816(acc[j][1], ah, bl[0][2], bl[0][3]);
                mma16816(acc[j][2], ah, bl[1][0], bl[1][1]);
                mma16816(acc[j][3], ah, bl[1][2], bl[1][3]);
                // lh
                mma16816(acc[j][0], al, bh[0][0], bh[0][1]);
                mma16816(acc[j][1], al, bh[0][2], bh[0][3]);
                mma16816(acc[j][2], al, bh[1][0], bh[1][1]);
                mma16816(acc[j][3], al, bh[1][2], bh[1][3]);
            }
        }

        // convert(t+1) while tensor pipe drains
        if (t + 1 < KI) convert(t + 1);
        __syncthreads();                                   // buffers free / conv visible

        if (t + 2 < KI) {
            issue_B(t + 2, t & 1);
            if (t + 3 < KI) issue_A(t + 3, (t + 1) & 1);
            cp_commit();
        }
    }

    // ---- epilogue: stage all tiles, partial dot, g_part ----
    __syncthreads();
    float* ep = reinterpret_cast<float*>(smem + g * EPI_MAT);
    #pragma unroll
    for (int j = 0; j < 7; ++j) {
        if (j < TC) {
            #pragma unroll
            for (int no = 0; no < 4; ++no) {
                const int row = j * 16 + (lane >> 2);
                const int col = colq * 32 + no * 8 + (lane & 3) * 2;
                *reinterpret_cast<float2*>(&ep[row * EPI_STRIDE + col]) =
                    make_float2(acc[j][no][0], acc[j][no][1]);
                *reinterpret_cast<float2*>(&ep[(row + 8) * EPI_STRIDE + col]) =
                    make_float2(acc[j][no][2], acc[j][no][3]);
            }
        }
    }
    __syncthreads();

    if (tid < 112 && (tid >> 4) < TC) {
        const float* Us = reinterpret_cast<const float*>(smem);
        const float* Es = reinterpret_cast<const float*>(smem + EPI_MAT);
        float ssum = 0.f;
        #pragma unroll
        for (int cb = 0; cb < 32; ++cb) {
            const int col = cb * 4;
            const float4 u  = *reinterpret_cast<const float4*>(&Us[tid * EPI_STRIDE + col]);
            const float4 e  = *reinterpret_cast<const float4*>(&Es[tid * EPI_STRIDE + col]);
            const float4 b1 = *reinterpret_cast<const float4*>(&bu[n0 + col]);
            const float4 b2 = *reinterpret_cast<const float4*>(&be[n0 + col]);
            ssum += (u.x + b1.x) * (e.x + b2.x)
                  + (u.y + b1.y) * (e.y + b2.y)
                  + (u.z + b1.z) * (e.z + b2.z)
                  + (u.w + b1.w) * (e.w + b2.w);
        }
        g_part[ntile][row_base + tid] = ssum;
    }
}

// ============ combine ============
__global__ void __launch_bounds__(256)
combine_kernel(float* __restrict__ out)
{
    const int i = blockIdx.x * 256 + threadIdx.x;
    const float l = g_part[0][i] + g_part[1][i];
    out[i] = 1.0f / (1.0f + expf(-l));
}

extern "C" void kernel_launch(void* const* d_in, const int* in_sizes, int n_in,
                              void* d_out, int out_size)
{
    const float* user  = (const float*)d_in[0];
    const float* event = (const float*)d_in[1];
    const float* Wu    = (const float*)d_in[2];
    const float* bu    = (const float*)d_in[3];
    const float* We    = (const float*)d_in[4];
    const float* be    = (const float*)d_in[5];
    float* out = (float*)d_out;

    cudaFuncSetAttribute(gemm_kernel, cudaFuncAttributeMaxDynamicSharedMemorySize, SMEM_SIZE);

    prep_kernel<<<512, 256>>>(Wu, We);
    gemm_kernel<<<148, 256, SMEM_SIZE>>>(user, event, bu, be);
    combine_kernel<<<N_ROWS / 256, 256>>>(out);
}

// round 11
// speedup vs baseline: 2.2754x; 1.0325x over previous
#include <cuda_runtime.h>
#include <cuda_fp16.h>
#include <cstdint>

#define N_ROWS 8192
#define K_DIM  512
#define J_DIM  256
#define KI     16          // k-iterations (32 k each)

// ---------------- smem layout (bytes) ----------------
// B:    2 stages x [m*2+h][128 n][80B]        = 2 x 40960 @ 0
// ARAW: 2 stages x [m][112 rows][128B]        = 2 x 28672 @ 81920
// ACONV:2 stages x [m][h][7 tiles][16][80B]   = 2 x 35840 @ 139264
#define B_ST      40960
#define ARAW_OFF  81920
#define ARAW_ST   28672
#define ACV_OFF   139264
#define ACV_ST    35840
#define SMEM_SIZE 210944
// epilogue staging (reuse region @0): [m][112 rows][132 floats]
#define EPI_STRIDE 132
#define EPI_MAT    59136

// ---------------- device scratch ----------------
__device__ __half g_B[2][2][J_DIM][K_DIM];   // [mat][hi/lo][n][k]
__device__ float  g_part[2][N_ROWS];
__device__ int    g_flag[74];

// ---------------- helpers ----------------
__device__ __forceinline__ uint32_t smem_u32(const void* p) {
    uint32_t a;
    asm("{ .reg .u64 t; cvta.to.shared.u64 t, %1; cvt.u32.u64 %0, t; }" : "=r"(a) : "l"(p));
    return a;
}
__device__ __forceinline__ void cp16(uint32_t sdst, const void* g) {
    asm volatile("cp.async.cg.shared.global [%0], [%1], 16;" :: "r"(sdst), "l"(g));
}
__device__ __forceinline__ void cp_commit() { asm volatile("cp.async.commit_group;"); }
template <int N>
__device__ __forceinline__ void cp_wait() { asm volatile("cp.async.wait_group %0;" :: "n"(N)); }

__device__ __forceinline__ void ldsm4(uint32_t (&r)[4], uint32_t addr) {
    asm volatile("ldmatrix.sync.aligned.m8n8.x4.shared.b16 {%0,%1,%2,%3}, [%4];"
        : "=r"(r[0]), "=r"(r[1]), "=r"(r[2]), "=r"(r[3]) : "r"(addr));
}
__device__ __forceinline__ void mma16816(float (&c)[4], const uint32_t (&a)[4],
                                         uint32_t b0, uint32_t b1) {
    asm volatile("mma.sync.aligned.m16n8k16.row.col.f32.f16.f16.f32 "
        "{%0,%1,%2,%3}, {%4,%5,%6,%7}, {%8,%9}, {%0,%1,%2,%3};"
        : "+f"(c[0]), "+f"(c[1]), "+f"(c[2]), "+f"(c[3])
        : "r"(a[0]), "r"(a[1]), "r"(a[2]), "r"(a[3]), "r"(b0), "r"(b1));
}
__device__ __forceinline__ uint32_t packh2(__half a, __half b) {
    __half2 h = __halves2half2(a, b);
    return *reinterpret_cast<uint32_t*>(&h);
}
__device__ __forceinline__ void split(float x, __half& hi, __half& lo) {
    hi = __float2half_rn(x);
    lo = __float2half_rn(x - __half2float(hi));
}

// ============ prep: smem-transpose W -> g_B, both sides coalesced ============
// 64 CTAs: m(2) x kc(16, 32k each) x nc(2, 128n each)
__global__ void __launch_bounds__(256)
prep_kernel(const float* __restrict__ Wu, const float* __restrict__ We)
{
    __shared__ float raw[32][128];            // 16KB, conflict-free by n
    const int bid = blockIdx.x;
    const int m  = bid >> 5;
    const int kc = (bid >> 1) & 15;
    const int nc = bid & 1;
    const int k0 = kc * 32, n0 = nc * 128;
    const float* W = m ? We : Wu;
    const int tid = threadIdx.x;

    // zero finisher flags (CTA 0) — must happen each graph replay
    if (bid == 0 && tid < 74) g_flag[tid] = 0;

    // stage raw [32 k][128 n] fp32, coalesced float4
    #pragma unroll
    for (int i = 0; i < 4; ++i) {
        const int e = tid + i * 256;          // 1024 float4
        const int k = e >> 5, n4 = (e & 31) * 4;
        cp16(smem_u32(&raw[k][n4]), &W[(size_t)(k0 + k) * J_DIM + n0 + n4]);
    }
    cp_commit();
    cp_wait<0>();
    __syncthreads();

    // convert: o = (n, kq): 128 x 8 = 1024 outputs, kq fastest -> coalesced stores
    #pragma unroll
    for (int i = 0; i < 4; ++i) {
        const int o = tid + i * 256;
        const int n = o >> 3, kq = o & 7;
        __half h0, l0, h1, l1, h2, l2, h3, l3;
        split(raw[kq * 4 + 0][n], h0, l0);
        split(raw[kq * 4 + 1][n], h1, l1);
        split(raw[kq * 4 + 2][n], h2, l2);
        split(raw[kq * 4 + 3][n], h3, l3);
        *reinterpret_cast<uint2*>(&g_B[m][0][n0 + n][k0 + kq * 4]) =
            make_uint2(packh2(h0, h1), packh2(h2, h3));
        *reinterpret_cast<uint2*>(&g_B[m][1][n0 + n][k0 + kq * 4]) =
            make_uint2(packh2(l0, l1), packh2(l2, l3));
    }
}

// ============ GEMM: 148 persistent CTAs, 112 rows x 128 cols, K-outer ============
__global__ void __launch_bounds__(256, 1)
gemm_kernel(const float* __restrict__ user, const float* __restrict__ event,
            const float* __restrict__ bu, const float* __restrict__ be,
            float* __restrict__ out)
{
    extern __shared__ __align__(1024) char smem[];
    const uint32_t sb = smem_u32(smem);
    const int tid  = threadIdx.x;
    const int wid  = tid >> 5;
    const int lane = tid & 31;

    const int ntile = (blockIdx.x >= 74) ? 1 : 0;
    const int b     = blockIdx.x - ntile * 74;
    const int r0    = (b < 68) ? 7 * b : 476 + 6 * (b - 68);   // rowtile base
    const int TC    = (b < 68) ? 7 : 6;                        // valid tiles
    const int n0    = ntile * 128;
    const int row_base = r0 * 16;

    const char* bflat = reinterpret_cast<const char*>(&g_B[0][0][0][0]);

    auto issue_B = [&](int t, int st) {
        #pragma unroll
        for (int i = 0; i < 8; ++i) {
            const int c = tid + i * 256;
            const int nrow = c >> 2, q = c & 3;
            const int m = nrow >> 8, h = (nrow >> 7) & 1, n = nrow & 127;
            cp16(sb + st * B_ST + nrow * 80 + q * 16,
                 bflat + ((size_t)((m * 2 + h) * J_DIM + n0 + n)) * (K_DIM * 2)
                       + (size_t)t * 64 + q * 16);
        }
    };
    auto issue_A = [&](int t, int st) {
        #pragma unroll
        for (int i = 0; i < 7; ++i) {
            const int e = tid + i * 256;
            const int m = (e >= 896) ? 1 : 0;
            const int rem = e - m * 896;
            const int row = rem >> 3, q = rem & 7;
            int rg = row_base + row;
            if (rg > N_ROWS - 1) rg = N_ROWS - 1;
            cp16(sb + ARAW_OFF + st * ARAW_ST + m * 14336 + row * 128 + q * 16,
                 (m ? event : user) + (size_t)rg * K_DIM + t * 32 + q * 4);
        }
    };
    auto convert = [&](int t) {
        const int st = t & 1;
        #pragma unroll
        for (int i = 0; i < 7; ++i) {
            const int e = tid + i * 256;
            const int m = (e >= 896) ? 1 : 0;
            const int rem = e - m * 896;
            const int row = rem >> 3, q = rem & 7;
            const float4 v = *reinterpret_cast<const float4*>(
                smem + ARAW_OFF + st * ARAW_ST + m * 14336 + row * 128 + q * 16);
            __half hx, lx, hy, ly, hz, lz, hw, lw;
            split(v.x, hx, lx); split(v.y, hy, ly);
            split(v.z, hz, lz); split(v.w, hw, lw);
            const int tile = row >> 4, lr = row & 15;
            const uint32_t base = ACV_OFF + st * ACV_ST + m * 17920
                                + tile * 1280 + lr * 80 + q * 8;
            *reinterpret_cast<uint2*>(smem + base) =
                make_uint2(packh2(hx, hy), packh2(hz, hw));
            *reinterpret_cast<uint2*>(smem + base + 8960) =
                make_uint2(packh2(lx, ly), packh2(lz, lw));
        }
    };

    const int g    = wid >> 2;
    const int colq = wid & 3;
    const uint32_t a_lane = (uint32_t)((lane & 15) * 80 + (lane >> 4) * 16);
    const uint32_t b_lane = (uint32_t)(((lane & 7) + ((lane >> 4) & 1) * 8 + colq * 32) * 80
                                       + ((lane >> 3) & 1) * 16);

    float acc[7][4][4];
    #pragma unroll
    for (int j = 0; j < 7; ++j)
        #pragma unroll
        for (int no = 0; no < 4; ++no)
            #pragma unroll
            for (int x = 0; x < 4; ++x) acc[j][no][x] = 0.f;

    // ---- prologue ----
    issue_A(0, 0); cp_commit();
    issue_B(0, 0); issue_A(1, 1); cp_commit();
    cp_wait<1>();
    __syncthreads();
    convert(0);
    __syncthreads();
    issue_B(1, 1); issue_A(2, 0); cp_commit();

    // ---- main loop ----
    for (int t = 0; t < KI; ++t) {
        const int st = t & 1;
        if (t < KI - 1) cp_wait<1>(); else cp_wait<0>();
        __syncthreads();

        const uint32_t aH = sb + ACV_OFF + st * ACV_ST + g * 17920 + a_lane;
        const uint32_t aL = aH + 8960;
        const uint32_t bH = sb + st * B_ST + g * 20480 + b_lane;
        const uint32_t bL = bH + 10240;
        #pragma unroll
        for (int ks = 0; ks < 2; ++ks) {
            const uint32_t kb = ks * 32;
            uint32_t bh[2][4], bl[2][4];
            ldsm4(bh[0], bH + kb);
            ldsm4(bh[1], bH + 1280 + kb);
            ldsm4(bl[0], bL + kb);
            ldsm4(bl[1], bL + 1280 + kb);
            #pragma unroll
            for (int j = 0; j < 7; ++j) {
                uint32_t ah[4], al[4];
                ldsm4(ah, aH + j * 1280 + kb);
                ldsm4(al, aL + j * 1280 + kb);
                mma16816(acc[j][0], ah, bh[0][0], bh[0][1]);
                mma16816(acc[j][1], ah, bh[0][2], bh[0][3]);
                mma16816(acc[j][2], ah, bh[1][0], bh[1][1]);
                mma16816(acc[j][3], ah, bh[1][2], bh[1][3]);
                mma16816(acc[j][0], ah, bl[0][0], bl[0][1]);
                mma16816(acc[j][1], ah, bl[0][2], bl[0][3]);
                mma16816(acc[j][2], ah, bl[1][0], bl[1][1]);
                mma16816(acc[j][3], ah, bl[1][2], bl[1][3]);
                mma16816(acc[j][0], al, bh[0][0], bh[0][1]);
                mma16816(acc[j][1], al, bh[0][2], bh[0][3]);
                mma16816(acc[j][2], al, bh[1][0], bh[1][1]);
                mma16816(acc[j][3], al, bh[1][2], bh[1][3]);
            }
        }

        if (t + 1 < KI) convert(t + 1);
        __syncthreads();

        if (t + 2 < KI) {
            issue_B(t + 2, t & 1);
            if (t + 3 < KI) issue_A(t + 3, (t + 1) & 1);
            cp_commit();
        }
    }

    // ---- epilogue: stage tiles, partial dot ----
    __syncthreads();
    float* ep = reinterpret_cast<float*>(smem + g * EPI_MAT);
    #pragma unroll
    for (int j = 0; j < 7; ++j) {
        if (j < TC) {
            #pragma unroll
            for (int no = 0; no < 4; ++no) {
                const int row = j * 16 + (lane >> 2);
                const int col = colq * 32 + no * 8 + (lane & 3) * 2;
                *reinterpret_cast<float2*>(&ep[row * EPI_STRIDE + col]) =
                    make_float2(acc[j][no][0], acc[j][no][1]);
                *reinterpret_cast<float2*>(&ep[(row + 8) * EPI_STRIDE + col]) =
                    make_float2(acc[j][no][2], acc[j][no][3]);
            }
        }
    }
    __syncthreads();

    const int nrows = TC * 16;
    if (tid < nrows) {
        const float* Us = reinterpret_cast<const float*>(smem);
        const float* Es = reinterpret_cast<const float*>(smem + EPI_MAT);
        float ssum = 0.f;
        #pragma unroll
        for (int cb = 0; cb < 32; ++cb) {
            const int col = cb * 4;
            const float4 u  = *reinterpret_cast<const float4*>(&Us[tid * EPI_STRIDE + col]);
            const float4 e  = *reinterpret_cast<const float4*>(&Es[tid * EPI_STRIDE + col]);
            const float4 b1 = *reinterpret_cast<const float4*>(&bu[n0 + col]);
            const float4 b2 = *reinterpret_cast<const float4*>(&be[n0 + col]);
            ssum += (u.x + b1.x) * (e.x + b2.x)
                  + (u.y + b1.y) * (e.y + b2.y)
                  + (u.z + b1.z) * (e.z + b2.z)
                  + (u.w + b1.w) * (e.w + b2.w);
        }
        g_part[ntile][row_base + tid] = ssum;
        __threadfence();                 // order partial before the flag
    }
    __syncthreads();

    // ---- split-N finisher: second CTA of the pair writes sigmoid ----
    int* flag_slot = reinterpret_cast<int*>(smem);   // EPI region consumed
    if (tid == 0)
        *flag_slot = atomicAdd(&g_flag[b], 1);
    __syncthreads();
    if (*flag_slot == 1 && tid < nrows) {
        __threadfence();                 // acquire partner's partial
        const int r = row_base + tid;
        const float l = g_part[0][r] + g_part[1][r];
        out[r] = 1.0f / (1.0f + expf(-l));
    }
}

extern "C" void kernel_launch(void* const* d_in, const int* in_sizes, int n_in,
                              void* d_out, int out_size)
{
    const float* user  = (const float*)d_in[0];
    const float* event = (const float*)d_in[1];
    const float* Wu    = (const float*)d_in[2];
    const float* bu    = (const float*)d_in[3];
    const float* We    = (const float*)d_in[4];
    const float* be    = (const float*)d_in[5];
    float* out = (float*)d_out;

    cudaFuncSetAttribute(gemm_kernel, cudaFuncAttributeMaxDynamicSharedMemorySize, SMEM_SIZE);

    prep_kernel<<<64, 256>>>(Wu, We);
    gemm_kernel<<<148, 256, SMEM_SIZE>>>(user, event, bu, be, out);
}